// round 10
// baseline (speedup 1.0000x reference)
#include <cuda_runtime.h>
#include <cuda_bf16.h>
#include <math.h>
#include <cstdint>

#define NROWS 8192
#define DDIM  64                  // feature dims
#define EDIM  96                  // + 32-slot class-spike block
#define NCLS  17
#define EPS 1e-8f
#define TILE 128
#define NTILES (NROWS / TILE)     // 64
#define NPREP  NTILES             // 64 prep blocks
#define NGROUPS 544               // sum over bi of ceil((64-bi)/4)
#define NWORKERS 296              // 2 CTAs/SM x 148 SMs, all wave-1 resident
#define ROWB 208                  // padded smem row stride (192B data + 16)
#define BUFB (TILE * ROWB)        // 26624 B per tile buffer
#define SMEM_TOTAL (4 * BUFB + 64)

// Scratch (no allocs allowed).
__device__ __align__(16) __nv_bfloat16 g_xA[NROWS * EDIM];  // spike +2
__device__ __align__(16) __nv_bfloat16 g_xB[NROWS * EDIM];  // spike -2
__device__ float    g_Spart[NPREP][DDIM];   // per-block fp32 row-sum partials
__device__ int      g_hist[NCLS];           // class histogram (reset each run)
__device__ double   g_accum;                // zero-init; last block resets
__device__ unsigned g_prep_done;            // idem
__device__ unsigned g_done_ctr;             // idem
__device__ unsigned g_work;                 // work cursor (reset each run)

__device__ __forceinline__ uint32_t smem_u32(const void* p) {
    uint32_t a;
    asm("{ .reg .u64 t; cvta.to.shared.u64 t, %1; cvt.u32.u64 %0, t; }"
        : "=r"(a) : "l"(p));
    return a;
}

__device__ __forceinline__ void ldsm_x4(uint32_t& r0, uint32_t& r1,
                                        uint32_t& r2, uint32_t& r3,
                                        uint32_t addr) {
    asm volatile("ldmatrix.sync.aligned.m8n8.x4.shared.b16 {%0,%1,%2,%3}, [%4];"
                 : "=r"(r0), "=r"(r1), "=r"(r2), "=r"(r3) : "r"(addr));
}

__device__ __forceinline__ void mma_16816(float* c, const uint32_t* a,
                                          uint32_t b0, uint32_t b1) {
    asm volatile(
        "mma.sync.aligned.m16n8k16.row.col.f32.bf16.bf16.f32 "
        "{%0,%1,%2,%3}, {%4,%5,%6,%7}, {%8,%9}, {%0,%1,%2,%3};"
        : "+f"(c[0]), "+f"(c[1]), "+f"(c[2]), "+f"(c[3])
        : "r"(a[0]), "r"(a[1]), "r"(a[2]), "r"(a[3]), "r"(b0), "r"(b1));
}

__device__ __forceinline__ void cpa16(uint32_t dst, const void* src) {
    asm volatile("cp.async.cg.shared.global [%0], [%1], 16;"
                 :: "r"(dst), "l"(src) : "memory");
}
#define CPA_COMMIT() asm volatile("cp.async.commit_group;" ::: "memory")
#define CPA_WAIT(n)  asm volatile("cp.async.wait_group %0;" :: "n"(n) : "memory")

// ---------------------------------------------------------------------------
// Persistent fused kernel. Rows carry class spikes: A side +2*e_c, B side
// -2*e_c, so the Gram yields v = cos - 4*same. Epilogue is compare-free fp32:
//   ACC = sum[ max(v,-0.1f) + max(v,-2f) ]
// and  loss*N^2 = 3*N_same - ||S||^2 + ACC + 0.1f*N^2
// with N_same from a class histogram and S = sum of fp32-normalized rows.
// ---------------------------------------------------------------------------
__global__ __launch_bounds__(256, 2) void fused_kernel(
    const float* __restrict__ x, const int* __restrict__ cls,
    float* __restrict__ out) {

    extern __shared__ __align__(16) char dsm[];
    char*  sA    = dsm;
    char*  sB    = dsm + BUFB;                    // 3 buffers of BUFB
    float* red   = (float*)(dsm + 4 * BUFB);
    int*   sunit = (int*)(red + 8);
    int*   sflag = sunit + 1;

    const int bid  = blockIdx.x;
    const int tid  = threadIdx.x;
    const int wid  = tid >> 5;
    const int lane = tid & 31;

    // ---------------- Phase 1: prep, blocks 0..63 ---------------------------
    if (bid < NPREP) {
        float* stage = (float*)dsm;               // [128][64] fp32, 32 KB
        int*   shist = (int*)(dsm + 128 * 64 * 4);
        if (tid < NCLS) shist[tid] = 0;
        __syncthreads();

        int t    = bid * 256 + tid;
        int row  = t >> 1;                        // global row
        int half = t & 1;
        int lrow = tid >> 1;                      // local row 0..127
        const float4* xr = (const float4*)(x + (size_t)row * DDIM + half * 32);
        float4 v[8];
        #pragma unroll
        for (int i = 0; i < 8; i++) v[i] = xr[i];
        float s = 0.0f;
        #pragma unroll
        for (int i = 0; i < 8; i++)
            s += v[i].x * v[i].x + v[i].y * v[i].y +
                 v[i].z * v[i].z + v[i].w * v[i].w;
        s += __shfl_xor_sync(0xffffffffu, s, 1);
        float inv = 1.0f / fmaxf(sqrtf(s), EPS);

        __nv_bfloat16* dA = g_xA + (size_t)row * EDIM + half * 32;
        __nv_bfloat16* dB = g_xB + (size_t)row * EDIM + half * 32;
        float* st = stage + lrow * DDIM + half * 32;
        #pragma unroll
        for (int i = 0; i < 8; i++) {
            float f0 = v[i].x * inv, f1 = v[i].y * inv;
            float f2 = v[i].z * inv, f3 = v[i].w * inv;
            __nv_bfloat162 p0 = {__float2bfloat16(f0), __float2bfloat16(f1)};
            __nv_bfloat162 p1 = {__float2bfloat16(f2), __float2bfloat16(f3)};
            *(__nv_bfloat162*)(dA + i * 4)     = p0;
            *(__nv_bfloat162*)(dA + i * 4 + 2) = p1;
            *(__nv_bfloat162*)(dB + i * 4)     = p0;
            *(__nv_bfloat162*)(dB + i * 4 + 2) = p1;
            st[i * 4 + 0] = f0; st[i * 4 + 1] = f1;
            st[i * 4 + 2] = f2; st[i * 4 + 3] = f3;
        }
        if (half == 0) {
            // spike blocks: 32 bf16 at offset DDIM; A=+2 at class, B=-2
            int c = cls[row];
            __nv_bfloat16* oA = g_xA + (size_t)row * EDIM + DDIM;
            __nv_bfloat16* oB = g_xB + (size_t)row * EDIM + DDIM;
            uint4 z = {0, 0, 0, 0};
            #pragma unroll
            for (int q = 0; q < 4; q++) {
                *(uint4*)(oA + q * 8) = z;
                *(uint4*)(oB + q * 8) = z;
            }
            oA[c] = __float2bfloat16(2.0f);
            oB[c] = __float2bfloat16(-2.0f);
            atomicAdd(&shist[c], 1);
        }
        __syncthreads();

        // Column sums of stage -> per-block S partial (64 dims)
        if (tid < DDIM) {
            float sd = 0.0f;
            #pragma unroll 8
            for (int r = 0; r < 128; r++) sd += stage[r * DDIM + tid];
            g_Spart[bid][tid] = sd;
        }
        if (tid < NCLS) atomicAdd(&g_hist[tid], shist[tid]);
        __syncthreads();
        if (tid == 0) { __threadfence(); atomicAdd(&g_prep_done, 1u); }
    }

    // ---------------- Device-wide wait for prep ----------------------------
    if (tid == 0) {
        unsigned v;
        do {
            asm volatile("ld.acquire.gpu.u32 %0, [%1];"
                         : "=r"(v) : "l"(&g_prep_done));
            if (v < (unsigned)NPREP) __nanosleep(64);
        } while (v < (unsigned)NPREP);
    }
    __syncthreads();

    const int wm = wid & 3;
    const int wn = wid >> 2;
    const uint32_t a_base = smem_u32(sA);
    const uint32_t bufu[3] = { smem_u32(sB), smem_u32(sB + BUFB),
                               smem_u32(sB + 2 * BUFB) };
    const uint32_t a_lane_off =
        (uint32_t)((wm * 32 + (lane & 15)) * ROWB + ((lane >> 4) << 4));
    const uint32_t b_lane_off =
        (uint32_t)((wn * 64 + (lane & 7) + ((lane >> 4) << 3)) * ROWB +
                   (((lane >> 3) & 1) << 4));

    float lsum = 0.0f;     // carried across ALL stolen groups

    // ==================== Persistent work-stealing loop =====================
    for (;;) {
        if (tid == 0) *sunit = (int)atomicAdd(&g_work, 1u);
        __syncthreads();
        const int unit = *sunit;
        if (unit >= NGROUPS) break;

        // ---- unit -> (bi, bj0, nb) ----
        int rem = unit, bi = 0;
        for (;;) {
            int g = (NTILES - bi + 3) >> 2;
            if (rem < g) break;
            rem -= g; bi++;
        }
        const int bj0 = bi + rem * 4;
        const int nb  = min(4, NTILES - bj0);

        // ---- Load A band (once per group): 128 x 192B = 1536 uint4 --------
        {
            const uint4* Ag = (const uint4*)(g_xA + (size_t)bi * TILE * EDIM);
            #pragma unroll
            for (int r = 0; r < 6; r++) {
                int idx = tid + r * 256;
                int row = idx / 12;
                int ch  = idx % 12;
                *(uint4*)(sA + row * ROWB + ch * 16) = Ag[idx];
            }
        }

        // ---- Prefetch B(0) (always from g_xB, even on diagonal) -----------
        {
            const char* src = (const char*)(g_xB + (size_t)bj0 * TILE * EDIM);
            #pragma unroll
            for (int r = 0; r < 6; r++) {
                int idx = tid + r * 256;
                int row = idx / 12;
                int ch  = idx % 12;
                cpa16(bufu[0] + row * ROWB + ch * 16, src + idx * 16);
            }
        }
        CPA_COMMIT();

        for (int t = 0; t < nb; t++) {
            if (t + 1 < nb) {
                const char* src =
                    (const char*)(g_xB + (size_t)(bj0 + t + 1) * TILE * EDIM);
                uint32_t dst = bufu[(t + 1) % 3];
                #pragma unroll
                for (int r = 0; r < 6; r++) {
                    int idx = tid + r * 256;
                    int row = idx / 12;
                    int ch  = idx % 12;
                    cpa16(dst + row * ROWB + ch * 16, src + idx * 16);
                }
                CPA_COMMIT();
                CPA_WAIT(1);
            } else {
                CPA_WAIT(0);
            }
            __syncthreads();

            const uint32_t b_base = bufu[t % 3];

            float c[2][8][4];
            #pragma unroll
            for (int m = 0; m < 2; m++)
                #pragma unroll
                for (int n = 0; n < 8; n++)
                    #pragma unroll
                    for (int e = 0; e < 4; e++) c[m][n][e] = 0.0f;

            #pragma unroll
            for (int k = 0; k < 6; k++) {     // 4 feature + 2 spike k-steps
                uint32_t a[2][4];
                #pragma unroll
                for (int m = 0; m < 2; m++)
                    ldsm_x4(a[m][0], a[m][1], a[m][2], a[m][3],
                            a_base + a_lane_off + m * 16 * ROWB + k * 32);
                uint32_t b[8][2];
                #pragma unroll
                for (int q = 0; q < 4; q++) {
                    uint32_t r0, r1, r2, r3;
                    ldsm_x4(r0, r1, r2, r3,
                            b_base + b_lane_off + q * 16 * ROWB + k * 32);
                    b[q * 2 + 0][0] = r0; b[q * 2 + 0][1] = r1;
                    b[q * 2 + 1][0] = r2; b[q * 2 + 1][1] = r3;
                }
                #pragma unroll
                for (int m = 0; m < 2; m++)
                    #pragma unroll
                    for (int n = 0; n < 8; n++)
                        mma_16816(c[m][n], a[m], b[n][0], b[n][1]);
            }

            // ---- Compare-free fp32 epilogue: 4 independent accumulators ----
            float a0 = 0.0f, a1 = 0.0f, a2 = 0.0f, a3 = 0.0f;
            #pragma unroll
            for (int m = 0; m < 2; m++)
                #pragma unroll
                for (int n = 0; n < 8; n++) {
                    float v0 = c[m][n][0], v1 = c[m][n][1];
                    float v2 = c[m][n][2], v3 = c[m][n][3];
                    a0 += fmaxf(v0, -0.1f) + fmaxf(v0, -2.0f);
                    a1 += fmaxf(v1, -0.1f) + fmaxf(v1, -2.0f);
                    a2 += fmaxf(v2, -0.1f) + fmaxf(v2, -2.0f);
                    a3 += fmaxf(v3, -0.1f) + fmaxf(v3, -2.0f);
                }
            float tl = (a0 + a1) + (a2 + a3);
            lsum += (bj0 + t == bi) ? tl : 2.0f * tl;
        }
        __syncthreads();   // all warps done with sA/buffers before next unit
    }

    // ---------------- One reduce + atomic per block --------------------------
    #pragma unroll
    for (int o = 16; o; o >>= 1) lsum += __shfl_xor_sync(0xffffffffu, lsum, o);
    if (lane == 0) red[wid] = lsum;
    __syncthreads();
    if (tid == 0) {
        float tt = 0.0f;
        #pragma unroll
        for (int w = 0; w < 8; w++) tt += red[w];
        atomicAdd(&g_accum, (double)tt);
        __threadfence();
        unsigned old = atomicAdd(&g_done_ctr, 1u);
        *sflag = (old == (unsigned)(NWORKERS - 1)) ? 1 : 0;
    }
    __syncthreads();

    // ---------------- Parallel finalize in the LAST block --------------------
    if (*sflag) {
        // ||S||^2: reduce 64 partials per dim, square, sum over dims.
        float sq = 0.0f;
        if (tid < DDIM) {
            float sd = 0.0f;
            #pragma unroll 8
            for (int b = 0; b < NPREP; b++) sd += g_Spart[b][tid];
            sq = sd * sd;
        }
        #pragma unroll
        for (int o = 16; o; o >>= 1) sq += __shfl_xor_sync(0xffffffffu, sq, o);
        if (lane == 0) red[wid] = sq;       // only wid 0,1 meaningful
        __syncthreads();
        if (tid == 0) {
            double snorm = (double)red[0] + (double)red[1];
            long long ns = 0;
            #pragma unroll
            for (int cc = 0; cc < NCLS; cc++) {
                long long h = (long long)g_hist[cc];
                ns += h * h;
                g_hist[cc] = 0;
            }
            double acc = atomicAdd(&g_accum, 0.0);
            double nn  = (double)NROWS * (double)NROWS;
            double total = 3.0 * (double)ns - snorm + acc
                         + (double)0.1f * nn;
            out[0] = (float)(total / nn);
            g_accum     = 0.0;
            g_done_ctr  = 0u;
            g_prep_done = 0u;
            g_work      = 0u;
        }
    }
}

extern "C" void kernel_launch(void* const* d_in, const int* in_sizes, int n_in,
                              void* d_out, int out_size) {
    const float* bottleneck = (const float*)d_in[0];
    const int*   class_map  = (const int*)d_in[1];
    float*       out        = (float*)d_out;

    cudaFuncSetAttribute(fused_kernel,
                         cudaFuncAttributeMaxDynamicSharedMemorySize,
                         SMEM_TOTAL);
    fused_kernel<<<NWORKERS, 256, SMEM_TOTAL>>>(bottleneck, class_map, out);
}

// round 11
// speedup vs baseline: 1.3703x; 1.3703x over previous
#include <cuda_runtime.h>
#include <cuda_bf16.h>
#include <math.h>
#include <cstdint>

#define NROWS 8192
#define DDIM  64
#define NCLS  17
#define MARGIN 1.1f
#define EPS 1e-8f
#define TILE 128
#define NTILES (NROWS / TILE)     // 64
#define NPREP  NTILES             // 64 prep blocks
#define NGROUPS 544               // sum over bi of ceil((64-bi)/4)
#define NWORKERS 296              // 2 CTAs/SM x 148 SMs, all wave-1 resident
#define ROWB 144                  // padded smem row stride (bytes)
#define BUFB (TILE * ROWB)        // 18432 bytes per tile buffer
// dsm layout: A | B0 | B1 | B2 | csi[128] | csj[512] | red[16] | unit | flag
#define SMEM_TOTAL (4 * BUFB + (128 + 512) * 4 + 64 + 16)

// Scratch (no allocs allowed).
__device__ __align__(16) __nv_bfloat16 g_xb[NROWS * DDIM];
__device__ double   g_accum;               // zero-init; last block resets
__device__ unsigned g_band_ready[NTILES];  // per-band prep flags (reset)
__device__ unsigned g_done_ctr;            // reset each run
__device__ unsigned g_work;                // work cursor (reset each run)
__device__ int      g_hist[NCLS];          // class histogram (reset each run)

__device__ __forceinline__ uint32_t smem_u32(const void* p) {
    uint32_t a;
    asm("{ .reg .u64 t; cvta.to.shared.u64 t, %1; cvt.u32.u64 %0, t; }"
        : "=r"(a) : "l"(p));
    return a;
}

__device__ __forceinline__ void ldsm_x4(uint32_t& r0, uint32_t& r1,
                                        uint32_t& r2, uint32_t& r3,
                                        uint32_t addr) {
    asm volatile("ldmatrix.sync.aligned.m8n8.x4.shared.b16 {%0,%1,%2,%3}, [%4];"
                 : "=r"(r0), "=r"(r1), "=r"(r2), "=r"(r3) : "r"(addr));
}

__device__ __forceinline__ void mma_16816(float* c, const uint32_t* a,
                                          uint32_t b0, uint32_t b1) {
    asm volatile(
        "mma.sync.aligned.m16n8k16.row.col.f32.bf16.bf16.f32 "
        "{%0,%1,%2,%3}, {%4,%5,%6,%7}, {%8,%9}, {%0,%1,%2,%3};"
        : "+f"(c[0]), "+f"(c[1]), "+f"(c[2]), "+f"(c[3])
        : "r"(a[0]), "r"(a[1]), "r"(a[2]), "r"(a[3]), "r"(b0), "r"(b1));
}

__device__ __forceinline__ void cpa16(uint32_t dst, const void* src) {
    asm volatile("cp.async.cg.shared.global [%0], [%1], 16;"
                 :: "r"(dst), "l"(src) : "memory");
}
#define CPA_COMMIT() asm volatile("cp.async.commit_group;" ::: "memory")
#define CPA_WAIT(n)  asm volatile("cp.async.wait_group %0;" :: "n"(n) : "memory")

// All threads spin (converged) until band b is published by its prep block.
__device__ __forceinline__ void wait_band(int b) {
    const unsigned* f = &g_band_ready[b];
    unsigned v;
    do {
        asm volatile("ld.acquire.gpu.u32 %0, [%1];" : "=r"(v) : "l"(f));
        if (!v) __nanosleep(64);
    } while (!v);
}

// ---------------------------------------------------------------------------
// Persistent fused kernel. Blocks 0..63 normalize their 128-row band -> bf16,
// histogram classes, and publish a per-band ready flag (no global barrier).
// All 296 blocks steal groups of up to 4 tiles sharing one A band, waiting
// only on the specific bands they read. Epilogue uses two accumulators:
//   same pair: accV += v        diff pair: accH += max(v + (M-1), 0)
// loss*N^2 = Sum(accH) - Sum(accV) + N_same   (N_same = sum h_c^2, exact).
// ---------------------------------------------------------------------------
__global__ __launch_bounds__(256, 2) void fused_kernel(
    const float* __restrict__ x, const int* __restrict__ cls,
    float* __restrict__ out) {

    extern __shared__ __align__(16) char dsm[];
    char*  sA    = dsm;
    char*  sB    = dsm + BUFB;                    // 3 buffers of BUFB
    int*   csi   = (int*)(dsm + 4 * BUFB);
    int*   csj   = csi + 128;                     // 4 x 128
    float* red   = (float*)(csj + 512);           // 16 floats
    int*   sunit = (int*)(red + 16);
    int*   sflag = sunit + 1;

    const int bid  = blockIdx.x;
    const int tid  = threadIdx.x;
    const int wid  = tid >> 5;
    const int lane = tid & 31;

    // ---------------- Phase 1: prep band bid (blocks 0..63) ----------------
    if (bid < NPREP) {
        int* shist = (int*)dsm;                   // transient; freed by sync
        if (tid < NCLS) shist[tid] = 0;
        __syncthreads();

        int t    = bid * 256 + tid;
        int row  = t >> 1;
        int half = t & 1;
        const float4* xr = (const float4*)(x + (size_t)row * DDIM + half * 32);
        float4 v[8];
        #pragma unroll
        for (int i = 0; i < 8; i++) v[i] = xr[i];
        float s = 0.0f;
        #pragma unroll
        for (int i = 0; i < 8; i++)
            s += v[i].x * v[i].x + v[i].y * v[i].y +
                 v[i].z * v[i].z + v[i].w * v[i].w;
        s += __shfl_xor_sync(0xffffffffu, s, 1);
        float inv = 1.0f / fmaxf(sqrtf(s), EPS);
        __nv_bfloat16* dst = g_xb + (size_t)row * DDIM + half * 32;
        #pragma unroll
        for (int i = 0; i < 8; i++) {
            __nv_bfloat162 p0 = {__float2bfloat16(v[i].x * inv),
                                 __float2bfloat16(v[i].y * inv)};
            __nv_bfloat162 p1 = {__float2bfloat16(v[i].z * inv),
                                 __float2bfloat16(v[i].w * inv)};
            *(__nv_bfloat162*)(dst + i * 4)     = p0;
            *(__nv_bfloat162*)(dst + i * 4 + 2) = p1;
        }
        if (half == 0) atomicAdd(&shist[cls[row]], 1);
        __syncthreads();
        if (tid < NCLS) atomicAdd(&g_hist[tid], shist[tid]);
        __syncthreads();
        if (tid == 0) {
            __threadfence();                      // publish band + hist
            atomicExch(&g_band_ready[bid], 1u);
        }
        __syncthreads();                          // shist dead before sA use
    }

    const int wm = wid & 3;
    const int wn = wid >> 2;
    const uint32_t a_base = smem_u32(sA);
    const uint32_t bufu[3] = { smem_u32(sB), smem_u32(sB + BUFB),
                               smem_u32(sB + 2 * BUFB) };
    const uint32_t a_lane_off =
        (uint32_t)((wm * 32 + (lane & 15)) * ROWB + ((lane >> 4) << 4));
    const uint32_t b_lane_off =
        (uint32_t)((wn * 64 + (lane & 7) + ((lane >> 4) << 3)) * ROWB +
                   (((lane >> 3) & 1) << 4));
    const float MC = MARGIN - 1.0f;
    const int quad = lane >> 2;
    const int tq   = lane & 3;

    float lsumH = 0.0f;    // hinge over diff pairs (weighted), all groups
    float lsumV = 0.0f;    // sum of v over same pairs (weighted), all groups

    // ==================== Persistent work-stealing loop =====================
    for (;;) {
        if (tid == 0) *sunit = (int)atomicAdd(&g_work, 1u);
        __syncthreads();
        const int unit = *sunit;
        if (unit >= NGROUPS) break;

        // ---- unit -> (bi, bj0, nb) ----
        int rem = unit, bi = 0;
        for (;;) {
            int g = (NTILES - bi + 3) >> 2;
            if (rem < g) break;
            rem -= g; bi++;
        }
        const int bj0 = bi + rem * 4;
        const int nb  = min(4, NTILES - bj0);

        // ---- Load A band + classes (wait only for band bi) ----
        wait_band(bi);
        {
            const uint4* Ag = (const uint4*)(g_xb + (size_t)bi * TILE * DDIM);
            #pragma unroll
            for (int r = 0; r < 4; r++) {
                int idx = tid + r * 256;
                int row = idx >> 3;
                int ch  = idx & 7;
                *(uint4*)(sA + row * ROWB + ch * 16) = Ag[idx];
            }
            if (tid < TILE) csi[tid] = __ldg(&cls[bi * TILE + tid]);
            for (int q = tid; q < nb * TILE; q += 256)
                csj[q] = __ldg(&cls[bj0 * TILE + q]);
        }

        // ---- Prefetch B(0) (wait only for band bj0) ----
        wait_band(bj0);
        {
            const char* src = (const char*)(g_xb + (size_t)bj0 * TILE * DDIM);
            #pragma unroll
            for (int r = 0; r < 4; r++) {
                int idx = tid + r * 256;
                int row = idx >> 3;
                int ch  = idx & 7;
                cpa16(bufu[0] + row * ROWB + ch * 16, src + idx * 16);
            }
        }
        CPA_COMMIT();
        __syncthreads();                 // csi/csj visible

        const int ci00 = csi[wm * 32 + quad];
        const int ci01 = csi[wm * 32 + quad + 8];
        const int ci10 = csi[wm * 32 + 16 + quad];
        const int ci11 = csi[wm * 32 + 16 + quad + 8];

        for (int t = 0; t < nb; t++) {
            if (t + 1 < nb) {
                wait_band(bj0 + t + 1);
                const char* src =
                    (const char*)(g_xb + (size_t)(bj0 + t + 1) * TILE * DDIM);
                uint32_t dst = bufu[(t + 1) % 3];
                #pragma unroll
                for (int r = 0; r < 4; r++) {
                    int idx = tid + r * 256;
                    int row = idx >> 3;
                    int ch  = idx & 7;
                    cpa16(dst + row * ROWB + ch * 16, src + idx * 16);
                }
                CPA_COMMIT();
                CPA_WAIT(1);
            } else {
                CPA_WAIT(0);
            }
            __syncthreads();

            const uint32_t b_base = bufu[t % 3];

            float c[2][8][4];
            #pragma unroll
            for (int m = 0; m < 2; m++)
                #pragma unroll
                for (int n = 0; n < 8; n++)
                    #pragma unroll
                    for (int e = 0; e < 4; e++) c[m][n][e] = 0.0f;

            #pragma unroll
            for (int k = 0; k < 4; k++) {
                uint32_t a[2][4];
                #pragma unroll
                for (int m = 0; m < 2; m++)
                    ldsm_x4(a[m][0], a[m][1], a[m][2], a[m][3],
                            a_base + a_lane_off + m * 16 * ROWB + k * 32);
                uint32_t b[8][2];
                #pragma unroll
                for (int q = 0; q < 4; q++) {
                    uint32_t r0, r1, r2, r3;
                    ldsm_x4(r0, r1, r2, r3,
                            b_base + b_lane_off + q * 16 * ROWB + k * 32);
                    b[q * 2 + 0][0] = r0; b[q * 2 + 0][1] = r1;
                    b[q * 2 + 1][0] = r2; b[q * 2 + 1][1] = r3;
                }
                #pragma unroll
                for (int m = 0; m < 2; m++)
                    #pragma unroll
                    for (int n = 0; n < 8; n++)
                        mma_16816(c[m][n], a[m], b[n][0], b[n][1]);
            }

            // ---- Dual-accumulator epilogue (5 instr/value) ----
            const int* cjt = csj + t * TILE;
            float tH = 0.0f, tV = 0.0f;
            #pragma unroll
            for (int m = 0; m < 2; m++) {
                const int ci0 = m ? ci10 : ci00;
                const int ci1 = m ? ci11 : ci01;
                #pragma unroll
                for (int n = 0; n < 8; n++) {
                    const int colb = wn * 64 + n * 8 + tq * 2;
                    const int cj0  = cjt[colb];
                    const int cj1  = cjt[colb + 1];
                    float v0 = c[m][n][0], v1 = c[m][n][1];
                    float v2 = c[m][n][2], v3 = c[m][n][3];
                    if (ci0 == cj0) tV += v0; else tH += fmaxf(v0 + MC, 0.0f);
                    if (ci0 == cj1) tV += v1; else tH += fmaxf(v1 + MC, 0.0f);
                    if (ci1 == cj0) tV += v2; else tH += fmaxf(v2 + MC, 0.0f);
                    if (ci1 == cj1) tV += v3; else tH += fmaxf(v3 + MC, 0.0f);
                }
            }
            if (bj0 + t == bi) { lsumH += tH;        lsumV += tV; }
            else               { lsumH += 2.0f * tH; lsumV += 2.0f * tV; }
        }
        __syncthreads();   // all warps done with sA/csj before next unit
    }

    // ---------------- One reduce + atomic per block --------------------------
    #pragma unroll
    for (int o = 16; o; o >>= 1) {
        lsumH += __shfl_xor_sync(0xffffffffu, lsumH, o);
        lsumV += __shfl_xor_sync(0xffffffffu, lsumV, o);
    }
    if (lane == 0) { red[wid] = lsumH; red[wid + 8] = lsumV; }
    __syncthreads();
    if (tid == 0) {
        float th = 0.0f, tv = 0.0f;
        #pragma unroll
        for (int w = 0; w < 8; w++) { th += red[w]; tv += red[w + 8]; }
        atomicAdd(&g_accum, (double)th - (double)tv);
        __threadfence();
        unsigned old = atomicAdd(&g_done_ctr, 1u);
        *sflag = (old == (unsigned)(NWORKERS - 1)) ? 1 : 0;
    }
    __syncthreads();

    // ---------------- Finalize in the LAST block ------------------------------
    if (*sflag) {
        if (tid == 0) {
            long long ns = 0;
            #pragma unroll
            for (int cc = 0; cc < NCLS; cc++) {
                long long h = (long long)g_hist[cc];
                ns += h * h;
                g_hist[cc] = 0;
            }
            double acc = atomicAdd(&g_accum, 0.0);
            double nn  = (double)NROWS * (double)NROWS;
            out[0] = (float)((acc + (double)ns) / nn);
            g_accum    = 0.0;
            g_done_ctr = 0u;
            g_work     = 0u;
        }
        if (tid < NTILES) g_band_ready[tid] = 0u;   // reset for next replay
    }
}

extern "C" void kernel_launch(void* const* d_in, const int* in_sizes, int n_in,
                              void* d_out, int out_size) {
    const float* bottleneck = (const float*)d_in[0];
    const int*   class_map  = (const int*)d_in[1];
    float*       out        = (float*)d_out;

    cudaFuncSetAttribute(fused_kernel,
                         cudaFuncAttributeMaxDynamicSharedMemorySize,
                         SMEM_TOTAL);
    fused_kernel<<<NWORKERS, 256, SMEM_TOTAL>>>(bottleneck, class_map, out);
}

// round 12
// speedup vs baseline: 1.4665x; 1.0703x over previous
#include <cuda_runtime.h>
#include <cuda_bf16.h>
#include <math.h>
#include <cstdint>

#define NROWS 8192
#define DDIM  64
#define NCLS  17
#define MARGIN 1.1f
#define EPS 1e-8f
#define TILE 128
#define NTILES (NROWS / TILE)     // 64
#define NPREP  NTILES             // 64 prep blocks
#define NGROUPS 544               // sum over bi of ceil((64-bi)/4)
#define NWORKERS 296              // 2 CTAs/SM x 148 SMs, all wave-1 resident
#define ROWB 144                  // padded smem row stride (bytes)
#define BUFB (TILE * ROWB)        // 18432 bytes per tile buffer
// dsm layout: A | B0 | B1 | B2 | csi[128] | csj[512] | red[8] | unit
#define SMEM_TOTAL (4 * BUFB + (128 + 512) * 4 + 32 + 16)

// Scratch (no allocs allowed).
__device__ __align__(16) __nv_bfloat16 g_xb[NROWS * DDIM];
__device__ double   g_accum;          // zero-init; last block resets
__device__ unsigned g_prep_done;      // idem
__device__ unsigned g_done_ctr;       // idem
__device__ unsigned g_work;           // work-stealing cursor (reset each run)

__device__ __forceinline__ uint32_t smem_u32(const void* p) {
    uint32_t a;
    asm("{ .reg .u64 t; cvta.to.shared.u64 t, %1; cvt.u32.u64 %0, t; }"
        : "=r"(a) : "l"(p));
    return a;
}

__device__ __forceinline__ void ldsm_x4(uint32_t& r0, uint32_t& r1,
                                        uint32_t& r2, uint32_t& r3,
                                        uint32_t addr) {
    asm volatile("ldmatrix.sync.aligned.m8n8.x4.shared.b16 {%0,%1,%2,%3}, [%4];"
                 : "=r"(r0), "=r"(r1), "=r"(r2), "=r"(r3) : "r"(addr));
}

__device__ __forceinline__ void mma_16816(float* c, const uint32_t* a,
                                          uint32_t b0, uint32_t b1) {
    asm volatile(
        "mma.sync.aligned.m16n8k16.row.col.f32.bf16.bf16.f32 "
        "{%0,%1,%2,%3}, {%4,%5,%6,%7}, {%8,%9}, {%0,%1,%2,%3};"
        : "+f"(c[0]), "+f"(c[1]), "+f"(c[2]), "+f"(c[3])
        : "r"(a[0]), "r"(a[1]), "r"(a[2]), "r"(a[3]), "r"(b0), "r"(b1));
}

__device__ __forceinline__ void cpa16(uint32_t dst, const void* src) {
    asm volatile("cp.async.cg.shared.global [%0], [%1], 16;"
                 :: "r"(dst), "l"(src) : "memory");
}
#define CPA_COMMIT() asm volatile("cp.async.commit_group;" ::: "memory")
#define CPA_WAIT(n)  asm volatile("cp.async.wait_group %0;" :: "n"(n) : "memory")

// ---------------------------------------------------------------------------
// Persistent fused kernel (296 resident CTAs). Blocks 0..63 normalize -> bf16
// (phase 1); all blocks steal GROUPS of up to 4 tiles sharing one A band.
// A FRAGMENTS ARE HELD IN REGISTERS for the whole group (loaded once), so the
// per-tile inner loop issues only B ldmatrix + HMMA. Loss accumulates in
// registers across groups; one reduce + atomic per block; last block
// finalizes the mean and resets state.
// ---------------------------------------------------------------------------
__global__ __launch_bounds__(256, 2) void fused_kernel(
    const float* __restrict__ x, const int* __restrict__ cls,
    float* __restrict__ out) {

    extern __shared__ __align__(16) char dsm[];
    char*  sA    = dsm;
    char*  sB    = dsm + BUFB;                    // 3 buffers of BUFB
    int*   csi   = (int*)(dsm + 4 * BUFB);
    int*   csj   = csi + 128;                     // 4 x 128
    float* red   = (float*)(csj + 512);
    int*   sunit = (int*)(red + 8);

    const int bid  = blockIdx.x;
    const int tid  = threadIdx.x;
    const int wid  = tid >> 5;
    const int lane = tid & 31;

    // ---------------- Phase 1: prep (normalize -> bf16), blocks 0..63 ------
    if (bid < NPREP) {
        int t    = bid * 256 + tid;
        int row  = t >> 1;
        int half = t & 1;
        const float4* xr = (const float4*)(x + (size_t)row * DDIM + half * 32);
        float4 v[8];
        #pragma unroll
        for (int i = 0; i < 8; i++) v[i] = xr[i];
        float s = 0.0f;
        #pragma unroll
        for (int i = 0; i < 8; i++)
            s += v[i].x * v[i].x + v[i].y * v[i].y +
                 v[i].z * v[i].z + v[i].w * v[i].w;
        s += __shfl_xor_sync(0xffffffffu, s, 1);
        float inv = 1.0f / fmaxf(sqrtf(s), EPS);
        __nv_bfloat16* dst = g_xb + (size_t)row * DDIM + half * 32;
        #pragma unroll
        for (int i = 0; i < 8; i++) {
            __nv_bfloat162 p0 = {__float2bfloat16(v[i].x * inv),
                                 __float2bfloat16(v[i].y * inv)};
            __nv_bfloat162 p1 = {__float2bfloat16(v[i].z * inv),
                                 __float2bfloat16(v[i].w * inv)};
            *(__nv_bfloat162*)(dst + i * 4)     = p0;
            *(__nv_bfloat162*)(dst + i * 4 + 2) = p1;
        }
        __syncthreads();
        if (tid == 0) { __threadfence(); atomicAdd(&g_prep_done, 1u); }
    }

    // ---------------- Device-wide wait for prep ----------------------------
    if (tid == 0) {
        unsigned v;
        do {
            asm volatile("ld.acquire.gpu.u32 %0, [%1];"
                         : "=r"(v) : "l"(&g_prep_done));
            if (v < (unsigned)NPREP) __nanosleep(64);
        } while (v < (unsigned)NPREP);
    }
    __syncthreads();

    const int wm = wid & 3;
    const int wn = wid >> 2;
    const uint32_t a_base = smem_u32(sA);
    const uint32_t bufu[3] = { smem_u32(sB), smem_u32(sB + BUFB),
                               smem_u32(sB + 2 * BUFB) };
    const uint32_t a_lane_off =
        (uint32_t)((wm * 32 + (lane & 15)) * ROWB + ((lane >> 4) << 4));
    const uint32_t b_lane_off =
        (uint32_t)((wn * 64 + (lane & 7) + ((lane >> 4) << 3)) * ROWB +
                   (((lane >> 3) & 1) << 4));
    const float MC = MARGIN - 1.0f;
    const int quad = lane >> 2;
    const int tq   = lane & 3;

    float lsum = 0.0f;     // carried across ALL stolen groups

    // ==================== Persistent work-stealing loop =====================
    for (;;) {
        if (tid == 0) *sunit = (int)atomicAdd(&g_work, 1u);
        __syncthreads();                 // broadcast unit; smem safe to reuse
        const int unit = *sunit;
        if (unit >= NGROUPS) break;

        // ---- unit -> (bi, bj0, nb) ----
        int rem = unit, bi = 0;
        for (;;) {
            int g = (NTILES - bi + 3) >> 2;
            if (rem < g) break;
            rem -= g; bi++;
        }
        const int bj0 = bi + rem * 4;
        const int nb  = min(4, NTILES - bj0);

        // ---- Load A band + classes (once per group) ----
        {
            const uint4* Ag = (const uint4*)(g_xb + (size_t)bi * TILE * DDIM);
            #pragma unroll
            for (int r = 0; r < 4; r++) {
                int idx = tid + r * 256;
                int row = idx >> 3;
                int ch  = idx & 7;
                *(uint4*)(sA + row * ROWB + ch * 16) = Ag[idx];
            }
            if (tid < TILE) csi[tid] = __ldg(&cls[bi * TILE + tid]);
            for (int q = tid; q < nb * TILE; q += 256)
                csj[q] = __ldg(&cls[bj0 * TILE + q]);
        }

        // ---- Prefetch B(0) ----
        {
            const char* src = (const char*)(g_xb + (size_t)bj0 * TILE * DDIM);
            #pragma unroll
            for (int r = 0; r < 4; r++) {
                int idx = tid + r * 256;
                int row = idx >> 3;
                int ch  = idx & 7;
                cpa16(bufu[0] + row * ROWB + ch * 16, src + idx * 16);
            }
        }
        CPA_COMMIT();
        __syncthreads();                 // sA + csi/csj visible

        // ---- A fragments: load ONCE per group, hold in registers ----
        uint32_t aF[4][2][4];            // [k][m][frag]
        #pragma unroll
        for (int k = 0; k < 4; k++)
            #pragma unroll
            for (int m = 0; m < 2; m++)
                ldsm_x4(aF[k][m][0], aF[k][m][1], aF[k][m][2], aF[k][m][3],
                        a_base + a_lane_off + m * 16 * ROWB + k * 32);

        // Row classes constant for the whole group: hoist.
        const int ci00 = csi[wm * 32 + quad];
        const int ci01 = csi[wm * 32 + quad + 8];
        const int ci10 = csi[wm * 32 + 16 + quad];
        const int ci11 = csi[wm * 32 + 16 + quad + 8];

        for (int t = 0; t < nb; t++) {
            if (t + 1 < nb) {
                const char* src =
                    (const char*)(g_xb + (size_t)(bj0 + t + 1) * TILE * DDIM);
                uint32_t dst = bufu[(t + 1) % 3];
                #pragma unroll
                for (int r = 0; r < 4; r++) {
                    int idx = tid + r * 256;
                    int row = idx >> 3;
                    int ch  = idx & 7;
                    cpa16(dst + row * ROWB + ch * 16, src + idx * 16);
                }
                CPA_COMMIT();
                CPA_WAIT(1);
            } else {
                CPA_WAIT(0);
            }
            __syncthreads();

            const uint32_t b_base = bufu[t % 3];

            float c[2][8][4];
            #pragma unroll
            for (int m = 0; m < 2; m++)
                #pragma unroll
                for (int n = 0; n < 8; n++)
                    #pragma unroll
                    for (int e = 0; e < 4; e++) c[m][n][e] = 0.0f;

            #pragma unroll
            for (int k = 0; k < 4; k++) {
                uint32_t b[8][2];
                #pragma unroll
                for (int q = 0; q < 4; q++) {
                    uint32_t r0, r1, r2, r3;
                    ldsm_x4(r0, r1, r2, r3,
                            b_base + b_lane_off + q * 16 * ROWB + k * 32);
                    b[q * 2 + 0][0] = r0; b[q * 2 + 0][1] = r1;
                    b[q * 2 + 1][0] = r2; b[q * 2 + 1][1] = r3;
                }
                #pragma unroll
                for (int m = 0; m < 2; m++)
                    #pragma unroll
                    for (int n = 0; n < 8; n++)
                        mma_16816(c[m][n], aF[k][m], b[n][0], b[n][1]);
            }

            // ---- Hinge epilogue on fragments (packed class loads) ----
            const int* cjt = csj + t * TILE;
            float l0 = 0.0f, l1 = 0.0f;
            #pragma unroll
            for (int m = 0; m < 2; m++) {
                const int ci0 = m ? ci10 : ci00;
                const int ci1 = m ? ci11 : ci01;
                #pragma unroll
                for (int n = 0; n < 8; n++) {
                    const int colb = wn * 64 + n * 8 + tq * 2;
                    const int2 cjp = *(const int2*)&cjt[colb];  // LDS.64
                    float v0 = c[m][n][0], v1 = c[m][n][1];
                    float v2 = c[m][n][2], v3 = c[m][n][3];
                    l0 += (ci0 == cjp.x) ? (1.0f - v0) : fmaxf(v0 + MC, 0.0f);
                    l1 += (ci0 == cjp.y) ? (1.0f - v1) : fmaxf(v1 + MC, 0.0f);
                    l0 += (ci1 == cjp.x) ? (1.0f - v2) : fmaxf(v2 + MC, 0.0f);
                    l1 += (ci1 == cjp.y) ? (1.0f - v3) : fmaxf(v3 + MC, 0.0f);
                }
            }
            float tl = l0 + l1;
            lsum += (bj0 + t == bi) ? tl : 2.0f * tl;
        }
        __syncthreads();   // all warps done with csi/csj/sA before next unit
    }

    // ---------------- One reduce + atomic per block --------------------------
    #pragma unroll
    for (int o = 16; o; o >>= 1) lsum += __shfl_xor_sync(0xffffffffu, lsum, o);
    if (lane == 0) red[wid] = lsum;
    __syncthreads();
    if (tid == 0) {
        float tt = 0.0f;
        #pragma unroll
        for (int w = 0; w < 8; w++) tt += red[w];
        atomicAdd(&g_accum, (double)tt);
        __threadfence();
        unsigned old = atomicAdd(&g_done_ctr, 1u);
        if (old == (unsigned)(NWORKERS - 1)) {
            double a = atomicAdd(&g_accum, 0.0);
            out[0] = (float)(a / ((double)NROWS * (double)NROWS));
            g_accum     = 0.0;
            g_done_ctr  = 0u;
            g_prep_done = 0u;
            g_work      = 0u;
        }
    }
}

extern "C" void kernel_launch(void* const* d_in, const int* in_sizes, int n_in,
                              void* d_out, int out_size) {
    const float* bottleneck = (const float*)d_in[0];
    const int*   class_map  = (const int*)d_in[1];
    float*       out        = (float*)d_out;

    cudaFuncSetAttribute(fused_kernel,
                         cudaFuncAttributeMaxDynamicSharedMemorySize,
                         SMEM_TOTAL);
    fused_kernel<<<NWORKERS, 256, SMEM_TOTAL>>>(bottleneck, class_map, out);
}